// round 4
// baseline (speedup 1.0000x reference)
#include <cuda_runtime.h>
#include <cstdint>

// SageConv: out = [features, (adj@features)/(rowsum(adj)+1)] @ W^T
// N=16384, D=256, OUT=256.
//
// K1: tf32 mma.sync GEMM  neigh = (adj @ features) / deg, deg fused from the
//     adj smem tiles (adj is read from HBM exactly once: BN covers all 256 cols).
// K2: tf32 mma.sync GEMM  out = concat(features, neigh) @ W^T  (K=512).

#define NN 16384
#define DD 256
#define OO 256

// 16 MB scratch for neigh (allocation-free rule: __device__ global).
__device__ float g_neigh[(size_t)NN * DD];

// ---------------- helpers ----------------
__device__ __forceinline__ uint32_t smem_u32(const void* p) {
    return (uint32_t)__cvta_generic_to_shared(p);
}
__device__ __forceinline__ void cp16(uint32_t dst, const void* src) {
    asm volatile("cp.async.cg.shared.global [%0], [%1], 16;\n" :: "r"(dst), "l"(src));
}
__device__ __forceinline__ void cp_commit() { asm volatile("cp.async.commit_group;\n"); }
template <int W_> __device__ __forceinline__ void cp_wait() {
    asm volatile("cp.async.wait_group %0;\n" :: "n"(W_));
}
__device__ __forceinline__ uint32_t f2tf(float x) {
    uint32_t r;
    asm("cvt.rna.tf32.f32 %0, %1;" : "=r"(r) : "f"(x));
    return r;
}
__device__ __forceinline__ void mma_tf32(float* d, const uint32_t* a, const uint32_t* b) {
    asm volatile(
        "mma.sync.aligned.m16n8k8.row.col.f32.tf32.tf32.f32 "
        "{%0,%1,%2,%3}, {%4,%5,%6,%7}, {%8,%9}, {%0,%1,%2,%3};"
        : "+f"(d[0]), "+f"(d[1]), "+f"(d[2]), "+f"(d[3])
        : "r"(a[0]), "r"(a[1]), "r"(a[2]), "r"(a[3]), "r"(b[0]), "r"(b[1]));
}

// ---------------- Kernel 1 ----------------
// BM=128, BN=256 (all of D), BK=32. 512 threads = 16 warps, warp tile 32x64.
// smem strides: A pad 36 floats -> (4r+c)%32 conflict-free for A frags;
//               B pad 260 floats -> (4k+n)%32 conflict-free for B frags.
#define SA 36
#define SB 260
#define A_BUF (128 * SA)   // 4608 floats
#define B_BUF (32 * SB)    // 8320 floats
#define SMEM1_FLOATS (2 * A_BUF + 2 * B_BUF)
#define SMEM1_BYTES (SMEM1_FLOATS * 4)

__global__ void __launch_bounds__(512, 1)
sage_k1(const float* __restrict__ features, const float* __restrict__ adj) {
    extern __shared__ float smem[];
    float* As = smem;                 // [2][128][SA]
    float* Bs = smem + 2 * A_BUF;     // [2][32][SB]

    const int tid  = threadIdx.x;
    const int lane = tid & 31;
    const int warp = tid >> 5;
    const int wm   = warp & 3;   // 4 m-tiles of 32
    const int wn   = warp >> 2;  // 4 n-tiles of 64
    const int rowBase = blockIdx.x * 128;

    float acc[2][8][4];
#pragma unroll
    for (int mt = 0; mt < 2; ++mt)
#pragma unroll
        for (int nt = 0; nt < 8; ++nt)
#pragma unroll
            for (int i = 0; i < 4; ++i) acc[mt][nt][i] = 0.f;

    const int rsrow = tid & 127;   // row this thread row-sums
    const int rsseg = tid >> 7;    // which 8-col segment
    float rs = 0.f;

    // tile loaders (each thread: 2 x 16B of adj, 4 x 16B of features)
    auto load_tile = [&](int kk, int buf) {
#pragma unroll
        for (int i = 0; i < 2; ++i) {
            int s = tid + i * 512;
            int r = s >> 3, c4 = s & 7;
            cp16(smem_u32(As + buf * A_BUF + r * SA + c4 * 4),
                 adj + (size_t)(rowBase + r) * NN + kk * 32 + c4 * 4);
        }
#pragma unroll
        for (int i = 0; i < 4; ++i) {
            int s = tid + i * 512;
            int kr = s >> 6, c4 = s & 63;
            cp16(smem_u32(Bs + buf * B_BUF + kr * SB + c4 * 4),
                 features + (size_t)(kk * 32 + kr) * DD + c4 * 4);
        }
    };

    load_tile(0, 0);
    cp_commit();

    for (int kk = 0; kk < 512; ++kk) {
        const int buf = kk & 1;
        if (kk + 1 < 512) {
            load_tile(kk + 1, buf ^ 1);
            cp_commit();
            cp_wait<1>();
        } else {
            cp_wait<0>();
        }
        __syncthreads();

        const float* A = As + buf * A_BUF;
        const float* B = Bs + buf * B_BUF;

        // fused degree: 8 floats of this thread's (row, segment)
        {
            float4 v0 = *(const float4*)(A + rsrow * SA + rsseg * 8);
            float4 v1 = *(const float4*)(A + rsrow * SA + rsseg * 8 + 4);
            rs += v0.x + v0.y + v0.z + v0.w + v1.x + v1.y + v1.z + v1.w;
        }

#pragma unroll
        for (int ks = 0; ks < 4; ++ks) {
            const int k = ks * 8;
            uint32_t af[2][4];
#pragma unroll
            for (int mt = 0; mt < 2; ++mt) {
                const int r0 = wm * 32 + mt * 16 + (lane >> 2);
                const int c0 = k + (lane & 3);
                af[mt][0] = f2tf(A[r0 * SA + c0]);
                af[mt][1] = f2tf(A[(r0 + 8) * SA + c0]);
                af[mt][2] = f2tf(A[r0 * SA + c0 + 4]);
                af[mt][3] = f2tf(A[(r0 + 8) * SA + c0 + 4]);
            }
            uint32_t bf[8][2];
#pragma unroll
            for (int nt = 0; nt < 8; ++nt) {
                const int n = wn * 64 + nt * 8 + (lane >> 2);
                bf[nt][0] = f2tf(B[(k + (lane & 3)) * SB + n]);
                bf[nt][1] = f2tf(B[(k + 4 + (lane & 3)) * SB + n]);
            }
#pragma unroll
            for (int mt = 0; mt < 2; ++mt)
#pragma unroll
                for (int nt = 0; nt < 8; ++nt)
                    mma_tf32(acc[mt][nt], af[mt], bf[nt]);
        }
        __syncthreads();
    }

    // reduce row sums -> deg, then scale + store neigh
    float* red = smem;           // reuse (512 partials)
    float* deg = smem + 512;     // 128 degrees
    red[rsseg * 128 + rsrow] = rs;
    __syncthreads();
    if (tid < 128)
        deg[tid] = red[tid] + red[128 + tid] + red[256 + tid] + red[384 + tid] + 1.0f;
    __syncthreads();

#pragma unroll
    for (int mt = 0; mt < 2; ++mt) {
        const int r0 = wm * 32 + mt * 16 + (lane >> 2);
        const float inv0 = 1.0f / deg[r0];
        const float inv1 = 1.0f / deg[r0 + 8];
#pragma unroll
        for (int nt = 0; nt < 8; ++nt) {
            const int c = wn * 64 + nt * 8 + (lane & 3) * 2;
            float2 o0 = make_float2(acc[mt][nt][0] * inv0, acc[mt][nt][1] * inv0);
            float2 o1 = make_float2(acc[mt][nt][2] * inv1, acc[mt][nt][3] * inv1);
            *(float2*)(g_neigh + (size_t)(rowBase + r0) * DD + c) = o0;
            *(float2*)(g_neigh + (size_t)(rowBase + r0 + 8) * DD + c) = o1;
        }
    }
}

// ---------------- Kernel 2 ----------------
// out[128 x 256] tile = concat(features,neigh)[128 x 512] @ W^T.
// BK=32, 16 k-iters (iters 0-7: features, 8-15: neigh). Single-buffered.
#define SMEM2_FLOATS (A_BUF + B_BUF)
#define SMEM2_BYTES (SMEM2_FLOATS * 4)

__global__ void __launch_bounds__(512, 1)
sage_k2(const float* __restrict__ features, const float* __restrict__ W,
        float* __restrict__ out) {
    extern __shared__ float smem[];
    float* Am = smem;            // [128][SA]
    float* Ws = smem + A_BUF;    // [32][SB]  Ws[k][o] = W[o][kk*32+k]

    const int tid  = threadIdx.x;
    const int lane = tid & 31;
    const int warp = tid >> 5;
    const int wm   = warp & 3;
    const int wn   = warp >> 2;
    const int rowBase = blockIdx.x * 128;

    float acc[2][8][4];
#pragma unroll
    for (int mt = 0; mt < 2; ++mt)
#pragma unroll
        for (int nt = 0; nt < 8; ++nt)
#pragma unroll
            for (int i = 0; i < 4; ++i) acc[mt][nt][i] = 0.f;

    for (int kk = 0; kk < 16; ++kk) {
        const float* srcA = (kk < 8) ? features : g_neigh;
        const int kb = (kk & 7) * 32;
        // A tile: 2 x float4 / thread
#pragma unroll
        for (int i = 0; i < 2; ++i) {
            int s = tid + i * 512;
            int r = s >> 3, c4 = s & 7;
            float4 v = *(const float4*)(srcA + (size_t)(rowBase + r) * DD + kb + c4 * 4);
            *(float4*)(Am + r * SA + c4 * 4) = v;
        }
        // W tile transposed into Ws[k][o]: 4 x float4 / thread
#pragma unroll
        for (int i = 0; i < 4; ++i) {
            int s = tid + i * 512;
            int n = s >> 3, c4 = s & 7;
            float4 v = *(const float4*)(W + (size_t)n * 512 + kk * 32 + c4 * 4);
            Ws[(c4 * 4 + 0) * SB + n] = v.x;
            Ws[(c4 * 4 + 1) * SB + n] = v.y;
            Ws[(c4 * 4 + 2) * SB + n] = v.z;
            Ws[(c4 * 4 + 3) * SB + n] = v.w;
        }
        __syncthreads();

#pragma unroll
        for (int ks = 0; ks < 4; ++ks) {
            const int k = ks * 8;
            uint32_t af[2][4];
#pragma unroll
            for (int mt = 0; mt < 2; ++mt) {
                const int r0 = wm * 32 + mt * 16 + (lane >> 2);
                const int c0 = k + (lane & 3);
                af[mt][0] = f2tf(Am[r0 * SA + c0]);
                af[mt][1] = f2tf(Am[(r0 + 8) * SA + c0]);
                af[mt][2] = f2tf(Am[r0 * SA + c0 + 4]);
                af[mt][3] = f2tf(Am[(r0 + 8) * SA + c0 + 4]);
            }
            uint32_t bf[8][2];
#pragma unroll
            for (int nt = 0; nt < 8; ++nt) {
                const int n = wn * 64 + nt * 8 + (lane >> 2);
                bf[nt][0] = f2tf(Ws[(k + (lane & 3)) * SB + n]);
                bf[nt][1] = f2tf(Ws[(k + 4 + (lane & 3)) * SB + n]);
            }
#pragma unroll
            for (int mt = 0; mt < 2; ++mt)
#pragma unroll
                for (int nt = 0; nt < 8; ++nt)
                    mma_tf32(acc[mt][nt], af[mt], bf[nt]);
        }
        __syncthreads();
    }

#pragma unroll
    for (int mt = 0; mt < 2; ++mt) {
        const int r0 = wm * 32 + mt * 16 + (lane >> 2);
#pragma unroll
        for (int nt = 0; nt < 8; ++nt) {
            const int c = wn * 64 + nt * 8 + (lane & 3) * 2;
            *(float2*)(out + (size_t)(rowBase + r0) * OO + c) =
                make_float2(acc[mt][nt][0], acc[mt][nt][1]);
            *(float2*)(out + (size_t)(rowBase + r0 + 8) * OO + c) =
                make_float2(acc[mt][nt][2], acc[mt][nt][3]);
        }
    }
}

// ---------------- launch ----------------
extern "C" void kernel_launch(void* const* d_in, const int* in_sizes, int n_in,
                              void* d_out, int out_size) {
    const float* features = (const float*)d_in[0];  // [16384, 256]
    const float* adj      = (const float*)d_in[1];  // [16384, 16384]
    const float* W        = (const float*)d_in[2];  // [256, 512]
    float* out = (float*)d_out;                     // [16384, 256]

    cudaFuncSetAttribute(sage_k1, cudaFuncAttributeMaxDynamicSharedMemorySize, SMEM1_BYTES);
    cudaFuncSetAttribute(sage_k2, cudaFuncAttributeMaxDynamicSharedMemorySize, SMEM2_BYTES);

    sage_k1<<<128, 512, SMEM1_BYTES>>>(features, adj);
    sage_k2<<<128, 512, SMEM2_BYTES>>>(features, W, out);
}

// round 9
// speedup vs baseline: 1.2315x; 1.2315x over previous
#include <cuda_runtime.h>
#include <cstdint>

// SageConv: out = [features, (adj@features)/(rowsum(adj)+1)] @ W^T
// N=16384, D=256, OUT=256.
//
// kR: element-wise RNA-tf32 rounding of features -> g_featR (B operand, no CVT in hot loop).
// K1: mma.sync tf32 GEMM  neigh = (adj @ features) / deg.
//     256 thr / 8 warps, warp tile 64x64, BM=128 BN=256 BK=32, 3-stage cp.async.
//     deg fused as FADDs on raw A-fragment floats (exact f32 rowsum, zero extra LDS).
// K2: mma.sync tf32 GEMM  out = concat(features, neigh) @ W^T  (K=512).

#define NN 16384
#define DD 256
#define OO 256

__device__ float g_neigh[(size_t)NN * DD];   // 16 MB scratch
__device__ float g_featR[(size_t)NN * DD];   // 16 MB: RNA-tf32-rounded features

// ---------------- helpers ----------------
__device__ __forceinline__ uint32_t smem_u32(const void* p) {
    return (uint32_t)__cvta_generic_to_shared(p);
}
__device__ __forceinline__ void cp16(uint32_t dst, const void* src) {
    asm volatile("cp.async.cg.shared.global [%0], [%1], 16;\n" :: "r"(dst), "l"(src));
}
__device__ __forceinline__ void cp_commit() { asm volatile("cp.async.commit_group;\n"); }
template <int W_> __device__ __forceinline__ void cp_wait() {
    asm volatile("cp.async.wait_group %0;\n" :: "n"(W_));
}
__device__ __forceinline__ uint32_t f2tf(float x) {
    uint32_t r;
    asm("cvt.rna.tf32.f32 %0, %1;" : "=r"(r) : "f"(x));
    return r;
}
__device__ __forceinline__ void mma_tf32(float* d, const uint32_t* a, const uint32_t* b) {
    asm volatile(
        "mma.sync.aligned.m16n8k8.row.col.f32.tf32.tf32.f32 "
        "{%0,%1,%2,%3}, {%4,%5,%6,%7}, {%8,%9}, {%0,%1,%2,%3};"
        : "+f"(d[0]), "+f"(d[1]), "+f"(d[2]), "+f"(d[3])
        : "r"(a[0]), "r"(a[1]), "r"(a[2]), "r"(a[3]), "r"(b[0]), "r"(b[1]));
}

// smem strides (floats). A-frag banks: (lane>>2)*4+(lane&3) unique.
// B-frag banks: (lane&3)*8+(lane>>2) unique (264%32==8). Conflict-free.
#define SA 36
#define SB 264
#define A_BUF (128 * SA)          // 4608 floats = 18432 B
#define B_BUF (32 * SB)           // 8448 floats = 33792 B

// ---------------- kR: RNA-tf32 round features ----------------
__global__ void __launch_bounds__(256)
sage_kR(const float* __restrict__ f) {
    const size_t i = ((size_t)blockIdx.x * 256 + threadIdx.x) * 4;
    float4 v = *(const float4*)(f + i);
    v.x = __uint_as_float(f2tf(v.x));
    v.y = __uint_as_float(f2tf(v.y));
    v.z = __uint_as_float(f2tf(v.z));
    v.w = __uint_as_float(f2tf(v.w));
    *(float4*)(g_featR + i) = v;
}

// ---------------- Kernel 1 ----------------
// 256 threads = 8 warps. wm = warp&1 (2 m-halves of 64), wn = warp>>1 (4 n-quarters of 64).
#define K1_STAGES 3
#define K1_STAGE_FLOATS (A_BUF + B_BUF)              // 13056 floats = 52224 B
#define SMEM1_BYTES (K1_STAGES * K1_STAGE_FLOATS * 4) // 156672 B

__global__ void __launch_bounds__(256, 1)
sage_k1(const float* __restrict__ adj) {
    extern __shared__ float smem[];

    const int tid  = threadIdx.x;
    const int lane = tid & 31;
    const int warp = tid >> 5;
    const int wm   = warp & 1;    // m-half (64 rows)
    const int wn   = warp >> 1;   // n-quarter (64 cols)
    const int rowBase = blockIdx.x * 128;

    float acc[4][8][4];
#pragma unroll
    for (int mt = 0; mt < 4; ++mt)
#pragma unroll
        for (int nt = 0; nt < 8; ++nt)
#pragma unroll
            for (int i = 0; i < 4; ++i) acc[mt][nt][i] = 0.f;

    float rs0[4], rs1[4];   // fused rowsum partials (rows r0, r0+8 per mt)
#pragma unroll
    for (int mt = 0; mt < 4; ++mt) { rs0[mt] = 0.f; rs1[mt] = 0.f; }

    // stage loader: A 1024 x 16B + B 2048 x 16B over 256 threads (12 each)
    auto load_stage = [&](int kk, int s) {
        float* As = smem + s * K1_STAGE_FLOATS;
        float* Bs = As + A_BUF;
#pragma unroll
        for (int i = 0; i < 4; ++i) {
            const int gid = tid + i * 256;           // 0..1023
            const int r = gid >> 3, c4 = gid & 7;
            cp16(smem_u32(As + r * SA + c4 * 4),
                 adj + (size_t)(rowBase + r) * NN + kk * 32 + c4 * 4);
        }
#pragma unroll
        for (int i = 0; i < 8; ++i) {
            const int g = tid + i * 256;             // 0..2047
            const int kr = g >> 6, c4 = g & 63;
            cp16(smem_u32(Bs + kr * SB + c4 * 4),
                 g_featR + (size_t)(kk * 32 + kr) * DD + c4 * 4);
        }
    };

    load_stage(0, 0); cp_commit();
    load_stage(1, 1); cp_commit();

    for (int kk = 0; kk < 512; ++kk) {
        __syncthreads();                 // prior iter's compute done before refill
        if (kk + 2 < 512) {
            load_stage(kk + 2, (kk + 2) % K1_STAGES);
            cp_commit();
        }
        if (kk < 510) cp_wait<2>();
        else if (kk == 510) cp_wait<1>();
        else cp_wait<0>();
        __syncthreads();                 // stage kk resident

        const float* A = smem + (kk % K1_STAGES) * K1_STAGE_FLOATS;
        const uint32_t* Bu = (const uint32_t*)(A + A_BUF);

#pragma unroll
        for (int ks = 0; ks < 4; ++ks) {
            const int k = ks * 8;
            uint32_t af[4][4];
#pragma unroll
            for (int mt = 0; mt < 4; ++mt) {
                const int r0 = wm * 64 + mt * 16 + (lane >> 2);
                const float* Ar = A + r0 * SA + k + (lane & 3);
                const float a0 = Ar[0];
                const float a1 = Ar[8 * SA];
                const float a2 = Ar[4];
                const float a3 = Ar[8 * SA + 4];
                if (ks == wn) {          // fused rowsum: exact f32, covers tile once
                    rs0[mt] += a0 + a2;
                    rs1[mt] += a1 + a3;
                }
                af[mt][0] = f2tf(a0); af[mt][1] = f2tf(a1);
                af[mt][2] = f2tf(a2); af[mt][3] = f2tf(a3);
            }
            uint32_t bf[8][2];
#pragma unroll
            for (int nt = 0; nt < 8; ++nt) {
                const int n = wn * 64 + nt * 8 + (lane >> 2);
                bf[nt][0] = Bu[(k + (lane & 3)) * SB + n];
                bf[nt][1] = Bu[(k + 4 + (lane & 3)) * SB + n];
            }
#pragma unroll
            for (int mt = 0; mt < 4; ++mt)
#pragma unroll
                for (int nt = 0; nt < 8; ++nt)
                    mma_tf32(acc[mt][nt], af[mt], bf[nt]);
        }
    }

    // ---- deg reduction: shfl over lane&3, then smem combine over wn ----
#pragma unroll
    for (int mt = 0; mt < 4; ++mt) {
        rs0[mt] += __shfl_xor_sync(0xffffffffu, rs0[mt], 1);
        rs0[mt] += __shfl_xor_sync(0xffffffffu, rs0[mt], 2);
        rs1[mt] += __shfl_xor_sync(0xffffffffu, rs1[mt], 1);
        rs1[mt] += __shfl_xor_sync(0xffffffffu, rs1[mt], 2);
    }
    __syncthreads();                     // stages dead; reuse smem
    float* red = smem;                   // [4][128]
    if ((lane & 3) == 0) {
#pragma unroll
        for (int mt = 0; mt < 4; ++mt) {
            const int r0 = wm * 64 + mt * 16 + (lane >> 2);
            red[wn * 128 + r0]     = rs0[mt];
            red[wn * 128 + r0 + 8] = rs1[mt];
        }
    }
    __syncthreads();
    float* deg = smem + 512;             // [128]
    if (tid < 128)
        deg[tid] = red[tid] + red[128 + tid] + red[256 + tid] + red[384 + tid] + 1.0f;
    __syncthreads();

    // ---- epilogue: neigh = acc / deg ----
#pragma unroll
    for (int mt = 0; mt < 4; ++mt) {
        const int r0 = wm * 64 + mt * 16 + (lane >> 2);
        const float inv0 = 1.0f / deg[r0];
        const float inv1 = 1.0f / deg[r0 + 8];
#pragma unroll
        for (int nt = 0; nt < 8; ++nt) {
            const int c = wn * 64 + nt * 8 + (lane & 3) * 2;
            *(float2*)(g_neigh + (size_t)(rowBase + r0) * DD + c) =
                make_float2(acc[mt][nt][0] * inv0, acc[mt][nt][1] * inv0);
            *(float2*)(g_neigh + (size_t)(rowBase + r0 + 8) * DD + c) =
                make_float2(acc[mt][nt][2] * inv1, acc[mt][nt][3] * inv1);
        }
    }
}

// ---------------- Kernel 2 ----------------
// out[128 x 256] = concat(features, neigh)[128 x 512] @ W^T, BK=32, 16 iters.
#define SMEM2_FLOATS (A_BUF + B_BUF)
#define SMEM2_BYTES (SMEM2_FLOATS * 4)

__global__ void __launch_bounds__(512, 1)
sage_k2(const float* __restrict__ features, const float* __restrict__ W,
        float* __restrict__ out) {
    extern __shared__ float smemf[];
    float* Am = smemf;
    float* Ws = smemf + A_BUF;

    const int tid  = threadIdx.x;
    const int lane = tid & 31;
    const int warp = tid >> 5;
    const int wm   = warp & 3;
    const int wn   = warp >> 2;
    const int rowBase = blockIdx.x * 128;

    float acc[2][8][4];
#pragma unroll
    for (int mt = 0; mt < 2; ++mt)
#pragma unroll
        for (int nt = 0; nt < 8; ++nt)
#pragma unroll
            for (int i = 0; i < 4; ++i) acc[mt][nt][i] = 0.f;

    for (int kk = 0; kk < 16; ++kk) {
        const float* srcA = (kk < 8) ? features : g_neigh;
        const int kb = (kk & 7) * 32;
#pragma unroll
        for (int i = 0; i < 2; ++i) {
            int s = tid + i * 512;
            int r = s >> 3, c4 = s & 7;
            float4 v = *(const float4*)(srcA + (size_t)(rowBase + r) * DD + kb + c4 * 4);
            *(float4*)(Am + r * SA + c4 * 4) = v;
        }
#pragma unroll
        for (int i = 0; i < 4; ++i) {
            int s = tid + i * 512;
            int n = s >> 3, c4 = s & 7;
            float4 v = *(const float4*)(W + (size_t)n * 512 + kk * 32 + c4 * 4);
            Ws[(c4 * 4 + 0) * SB + n] = v.x;
            Ws[(c4 * 4 + 1) * SB + n] = v.y;
            Ws[(c4 * 4 + 2) * SB + n] = v.z;
            Ws[(c4 * 4 + 3) * SB + n] = v.w;
        }
        __syncthreads();

#pragma unroll
        for (int ks = 0; ks < 4; ++ks) {
            const int k = ks * 8;
            uint32_t af[2][4];
#pragma unroll
            for (int mt = 0; mt < 2; ++mt) {
                const int r0 = wm * 32 + mt * 16 + (lane >> 2);
                const int c0 = k + (lane & 3);
                af[mt][0] = f2tf(Am[r0 * SA + c0]);
                af[mt][1] = f2tf(Am[(r0 + 8) * SA + c0]);
                af[mt][2] = f2tf(Am[r0 * SA + c0 + 4]);
                af[mt][3] = f2tf(Am[(r0 + 8) * SA + c0 + 4]);
            }
            uint32_t bf[8][2];
#pragma unroll
            for (int nt = 0; nt < 8; ++nt) {
                const int n = wn * 64 + nt * 8 + (lane >> 2);
                bf[nt][0] = f2tf(Ws[(k + (lane & 3)) * SB + n]);
                bf[nt][1] = f2tf(Ws[(k + 4 + (lane & 3)) * SB + n]);
            }
#pragma unroll
            for (int mt = 0; mt < 2; ++mt)
#pragma unroll
                for (int nt = 0; nt < 8; ++nt)
                    mma_tf32(acc[mt][nt], af[mt], bf[nt]);
        }
        __syncthreads();
    }

#pragma unroll
    for (int mt = 0; mt < 2; ++mt) {
        const int r0 = wm * 32 + mt * 16 + (lane >> 2);
#pragma unroll
        for (int nt = 0; nt < 8; ++nt) {
            const int c = wn * 64 + nt * 8 + (lane & 3) * 2;
            *(float2*)(out + (size_t)(rowBase + r0) * OO + c) =
                make_float2(acc[mt][nt][0], acc[mt][nt][1]);
            *(float2*)(out + (size_t)(rowBase + r0 + 8) * OO + c) =
                make_float2(acc[mt][nt][2], acc[mt][nt][3]);
        }
    }
}

// ---------------- launch ----------------
extern "C" void kernel_launch(void* const* d_in, const int* in_sizes, int n_in,
                              void* d_out, int out_size) {
    const float* features = (const float*)d_in[0];  // [16384, 256]
    const float* adj      = (const float*)d_in[1];  // [16384, 16384]
    const float* W        = (const float*)d_in[2];  // [256, 512]
    float* out = (float*)d_out;                     // [16384, 256]

    cudaFuncSetAttribute(sage_k1, cudaFuncAttributeMaxDynamicSharedMemorySize, SMEM1_BYTES);
    cudaFuncSetAttribute(sage_k2, cudaFuncAttributeMaxDynamicSharedMemorySize, SMEM2_BYTES);

    sage_kR<<<(NN * DD) / 1024, 256>>>(features);
    sage_k1<<<128, 256, SMEM1_BYTES>>>(adj);
    sage_k2<<<128, 512, SMEM2_BYTES>>>(features, W, out);
}